// round 14
// baseline (speedup 1.0000x reference)
#include <cuda_runtime.h>

#define Tv 512
#define ROWW 60    // 56 data + 4 pad floats per seq row (240B)
#define MROWW 12   // 8 ints + 4 pad per seq row
#define EFLOATS (64 * ROWW)
#define MINTS   (64 * MROWW)

__device__ float gA[8192 * 8];
__device__ float gU[8192 * 8];
__device__ int   gXF[8192], gXB[8192];
__device__ float gNF[8192], gNB[8192];
__device__ int   gCF[8192], gCB[8192];

typedef unsigned long long u64;

static __device__ __forceinline__ u64 PK(float a, float b) {
    u64 r; asm("mov.b64 %0,{%1,%2};" : "=l"(r) : "r"(__float_as_uint(a)), "r"(__float_as_uint(b))); return r;
}
static __device__ __forceinline__ void UPK(u64 v, float& a, float& b) {
    unsigned x, y; asm("mov.b64 {%0,%1},%2;" : "=r"(x), "=r"(y) : "l"(v));
    a = __uint_as_float(x); b = __uint_as_float(y);
}
static __device__ __forceinline__ u64 FMA2(u64 a, u64 b, u64 c) {
    u64 d; asm("fma.rn.f32x2 %0,%1,%2,%3;" : "=l"(d) : "l"(a), "l"(b), "l"(c)); return d;
}
static __device__ __forceinline__ u64 MUL2(u64 a, u64 b) {
    u64 d; asm("mul.rn.f32x2 %0,%1,%2;" : "=l"(d) : "l"(a), "l"(b)); return d;
}
static __device__ __forceinline__ void cpa16(void* dst, const void* src) {
    unsigned d = (unsigned)__cvta_generic_to_shared(dst);
    asm volatile("cp.async.cg.shared.global [%0], [%1], 16;" :: "r"(d), "l"(src));
}
#define CP_COMMIT() asm volatile("cp.async.commit_group;")
#define CP_WAIT2()  asm volatile("cp.async.wait_group 2;")

__global__ void __launch_bounds__(32, 1)
crf_half_kernel(const float* __restrict__ em,
                const int* __restrict__ labels,
                const int* __restrict__ mask,
                const float* __restrict__ startT,
                const float* __restrict__ endT,
                const float* __restrict__ trans)
{
    __shared__ float ES[3 * EFLOATS];
    __shared__ int   MS[3 * MINTS];
    __shared__ int   LS[3 * MINTS];
    __shared__ float STRs[49];

    const int lane  = threadIdx.x;
    const int half  = blockIdx.x >> 7;       // 0 = forward, 1 = backward
    const int group = blockIdx.x & 127;      // 64-seq group
    const int seqA  = group * 64 + lane;
    const int seqB  = seqA + 32;

    const float* emb  = em + (size_t)(group * 64) * (Tv * 7);
    const int*   labb = labels + (size_t)(group * 64) * Tv;
    const int*   mskb = mask   + (size_t)(group * 64) * Tv;

    for (int i = lane; i < 49; i += 32) STRs[i] = trans[i];
    __syncwarp();

    u64 EE[7][7];
#pragma unroll
    for (int i = 0; i < 7; i++)
#pragma unroll
        for (int j = 0; j < 7; j++) {
            float e = __expf(__ldg(&trans[i * 7 + j]));
            EE[i][j] = PK(e, e);
        }

#define STAGE(SLOT, MM) do { \
    float* _eb = ES + (SLOT) * EFLOATS; \
    int*   _mb = MS + (SLOT) * MINTS; \
    int*   _lb = LS + (SLOT) * MINTS; \
    _Pragma("unroll") \
    for (int i = 0; i < 28; i++) { \
        int idx = i * 32 + lane; int r = (idx * 4682) >> 16; int c = idx - r * 14; \
        cpa16(_eb + r * ROWW + c * 4, emb + (size_t)r * (Tv * 7) + (MM) * 56 + c * 4); \
    } \
    _Pragma("unroll") \
    for (int i = 0; i < 4; i++) { \
        int idx = i * 32 + lane; int s = idx >> 1; int h = idx & 1; \
        cpa16(_mb + s * MROWW + h * 4, mskb + (size_t)s * Tv + (MM) * 8 + h * 4); \
        cpa16(_lb + s * MROWW + h * 4, labb + (size_t)s * Tv + (MM) * 8 + h * 4); \
    } \
    CP_COMMIT(); } while (0)

    u64 p[7];
    int xsA = 0, xsB = 0;
    float numA = 0.f, numB = 0.f;
    int cntA = 0, cntB = 0;

#define RENORM() do { \
    float aA[7], aB[7]; \
    _Pragma("unroll") for (int j = 0; j < 7; j++) UPK(p[j], aA[j], aB[j]); \
    float mxA = aA[0], mxB = aB[0]; \
    _Pragma("unroll") for (int j = 1; j < 7; j++) { mxA = fmaxf(mxA, aA[j]); mxB = fmaxf(mxB, aB[j]); } \
    int exA = (__float_as_int(mxA) >> 23) & 0xFF; \
    int exB = (__float_as_int(mxB) >> 23) & 0xFF; \
    float invA = __int_as_float((254 - exA) << 23); \
    float invB = __int_as_float((254 - exB) << 23); \
    xsA += exA - 127; xsB += exB - 127; \
    u64 iv = PK(invA, invB); \
    _Pragma("unroll") for (int j = 0; j < 7; j++) p[j] = MUL2(p[j], iv); } while (0)

    if (half == 0) {
        // ======================= FORWARD: t in [0,256) =======================
        auto FSTEP = [&](const float* eA, const float* eB) {
            u64 q[7];
#pragma unroll
            for (int j = 0; j < 7; j++) q[j] = MUL2(p[0], EE[0][j]);
#pragma unroll
            for (int i = 1; i < 7; i++)
#pragma unroll
                for (int j = 0; j < 7; j++) q[j] = FMA2(p[i], EE[i][j], q[j]);
#pragma unroll
            for (int j = 0; j < 7; j++)
                p[j] = MUL2(q[j], PK(__expf(eA[j]), __expf(eB[j])));
        };
        auto SSTEP = [&](const float* eA, const float* eB, int MA, int MB) {
            u64 q[7];
#pragma unroll
            for (int j = 0; j < 7; j++) q[j] = MUL2(p[0], EE[0][j]);
#pragma unroll
            for (int i = 1; i < 7; i++)
#pragma unroll
                for (int j = 0; j < 7; j++) q[j] = FMA2(p[i], EE[i][j], q[j]);
#pragma unroll
            for (int j = 0; j < 7; j++)
                q[j] = MUL2(q[j], PK(__expf(eA[j]), __expf(eB[j])));
            u64 mm = ((u64)(MB ? 0xFFFFFFFFu : 0u) << 32) | (MA ? 0xFFFFFFFFu : 0u);
#pragma unroll
            for (int j = 0; j < 7; j++) p[j] = (q[j] & mm) | (p[j] & ~mm);
        };

        STAGE(0, 0); STAGE(1, 1); STAGE(2, 2);
        CP_WAIT2(); __syncwarp();

        int carryA = 0, carryB = 0;
#pragma unroll 1
        for (int m = 0; m < 32; m++) {
            if (m > 0) { CP_WAIT2(); __syncwarp(); }
            int st = m % 3;
            const float* rA = ES + st * EFLOATS + lane * ROWW;
            const float* rB = rA + 32 * ROWW;
            const int* mrA = MS + st * MINTS + lane * MROWW;
            const int* mrB = mrA + 32 * MROWW;
            const int* lrA = LS + st * MINTS + lane * MROWW;
            const int* lrB = lrA + 32 * MROWW;

            int4 xa0 = *(const int4*)(mrA), xa1 = *(const int4*)(mrA + 4);
            int4 xb0 = *(const int4*)(mrB), xb1 = *(const int4*)(mrB + 4);
            int am = xa0.x&xa0.y&xa0.z&xa0.w&xa1.x&xa1.y&xa1.z&xa1.w
                   & xb0.x&xb0.y&xb0.z&xb0.w&xb1.x&xb1.y&xb1.z&xb1.w;
            int fast = __all_sync(0xFFFFFFFFu, am);

            // ---- numerator (chain-free, carried adjacent labels) ----
            int PA = carryA, PB = carryB;
#pragma unroll
            for (int s = 0; s < 8; s++) {
                int LA = lrA[s]; LA = LA < 0 ? 0 : LA;
                int LB = lrB[s]; LB = LB < 0 ? 0 : LB;
                if (m == 0 && s == 0) {
                    numA = __ldg(startT + LA) + rA[LA];  cntA++;
                    numB = __ldg(startT + LB) + rB[LB];  cntB++;
                } else if (fast) {
                    numA += STRs[PA * 7 + LA] + rA[s * 7 + LA];  cntA++;
                    numB += STRs[PB * 7 + LB] + rB[s * 7 + LB];  cntB++;
                } else {
                    int MA = mrA[s], MB = mrB[s];
                    float vA = STRs[PA * 7 + LA] + rA[s * 7 + LA];
                    float vB = STRs[PB * 7 + LB] + rB[s * 7 + LB];
                    numA += MA ? vA : 0.f;  cntA += MA ? 1 : 0;
                    numB += MB ? vB : 0.f;  cntB += MB ? 1 : 0;
                }
                PA = LA; PB = LB;
            }
            carryA = PA; carryB = PB;

            // ---- recursion ----
            if (m == 0) {
                float qA[7], qB[7];
#pragma unroll
                for (int j = 0; j < 7; j++) {
                    float s0 = __ldg(startT + j);
                    qA[j] = __expf(s0 + rA[j]);
                    qB[j] = __expf(s0 + rB[j]);
                }
                float mxA = qA[0], mxB = qB[0];
#pragma unroll
                for (int j = 1; j < 7; j++) { mxA = fmaxf(mxA, qA[j]); mxB = fmaxf(mxB, qB[j]); }
                int exA = (__float_as_int(mxA) >> 23) & 0xFF;
                int exB = (__float_as_int(mxB) >> 23) & 0xFF;
                float invA = __int_as_float((254 - exA) << 23);
                float invB = __int_as_float((254 - exB) << 23);
                xsA = exA - 127; xsB = exB - 127;
#pragma unroll
                for (int j = 0; j < 7; j++) p[j] = PK(qA[j] * invA, qB[j] * invB);
#pragma unroll
                for (int s = 1; s < 8; s++) SSTEP(rA + s * 7, rB + s * 7, mrA[s], mrB[s]);
            } else if (fast) {
#pragma unroll
                for (int s = 0; s < 8; s++) FSTEP(rA + s * 7, rB + s * 7);
            } else {
#pragma unroll
                for (int s = 0; s < 8; s++) SSTEP(rA + s * 7, rB + s * 7, mrA[s], mrB[s]);
            }
            RENORM();
            __syncwarp();
            if (m + 3 < 32) STAGE((m + 3) % 3, m + 3); else CP_COMMIT();
        }

        // ---- publish alpha ----
        float aA[7], aB[7];
#pragma unroll
        for (int j = 0; j < 7; j++) UPK(p[j], aA[j], aB[j]);
#pragma unroll
        for (int j = 0; j < 7; j++) { gA[seqA * 8 + j] = aA[j]; gA[seqB * 8 + j] = aB[j]; }
        gXF[seqA] = xsA; gXF[seqB] = xsB;
        gNF[seqA] = numA; gNF[seqB] = numB;
        gCF[seqA] = cntA; gCF[seqB] = cntB;

    } else {
        // ======================= BACKWARD: t in [256,512) =======================
        auto BFSTEP = [&](const float* eA, const float* eB) {
            u64 w[7];
#pragma unroll
            for (int j = 0; j < 7; j++)
                w[j] = MUL2(p[j], PK(__expf(eA[j]), __expf(eB[j])));
            u64 q[7];
#pragma unroll
            for (int i = 0; i < 7; i++) q[i] = MUL2(w[0], EE[i][0]);
#pragma unroll
            for (int j = 1; j < 7; j++)
#pragma unroll
                for (int i = 0; i < 7; i++) q[i] = FMA2(w[j], EE[i][j], q[i]);
#pragma unroll
            for (int i = 0; i < 7; i++) p[i] = q[i];
        };
        auto BSSTEP = [&](const float* eA, const float* eB, int MA, int MB) {
            u64 w[7];
#pragma unroll
            for (int j = 0; j < 7; j++)
                w[j] = MUL2(p[j], PK(__expf(eA[j]), __expf(eB[j])));
            u64 q[7];
#pragma unroll
            for (int i = 0; i < 7; i++) q[i] = MUL2(w[0], EE[i][0]);
#pragma unroll
            for (int j = 1; j < 7; j++)
#pragma unroll
                for (int i = 0; i < 7; i++) q[i] = FMA2(w[j], EE[i][j], q[i]);
            u64 mm = ((u64)(MB ? 0xFFFFFFFFu : 0u) << 32) | (MA ? 0xFFFFFFFFu : 0u);
#pragma unroll
            for (int i = 0; i < 7; i++) p[i] = (q[i] & mm) | (p[i] & ~mm);
        };

        int L255A = __ldg(labb + (size_t)lane * Tv + 255);
        int L255B = __ldg(labb + (size_t)(lane + 32) * Tv + 255);
        L255A = L255A < 0 ? 0 : L255A;
        L255B = L255B < 0 ? 0 : L255B;

#pragma unroll
        for (int j = 0; j < 7; j++) { float e = __expf(__ldg(endT + j)); p[j] = PK(e, e); }

        STAGE(0, 63); STAGE(1, 62); STAGE(2, 61);
        CP_WAIT2(); __syncwarp();

        int pendLA = 0, pendMA = 0, pendLB = 0, pendMB = 0;
#pragma unroll 1
        for (int k = 0; k < 32; k++) {
            if (k > 0) { CP_WAIT2(); __syncwarp(); }
            int st = k % 3;
            const float* rA = ES + st * EFLOATS + lane * ROWW;
            const float* rB = rA + 32 * ROWW;
            const int* mrA = MS + st * MINTS + lane * MROWW;
            const int* mrB = mrA + 32 * MROWW;
            const int* lrA = LS + st * MINTS + lane * MROWW;
            const int* lrB = lrA + 32 * MROWW;

            int4 xa0 = *(const int4*)(mrA), xa1 = *(const int4*)(mrA + 4);
            int4 xb0 = *(const int4*)(mrB), xb1 = *(const int4*)(mrB + 4);
            int am = xa0.x&xa0.y&xa0.z&xa0.w&xa1.x&xa1.y&xa1.z&xa1.w
                   & xb0.x&xb0.y&xb0.z&xb0.w&xb1.x&xb1.y&xb1.z&xb1.w;
            int fast = __all_sync(0xFFFFFFFFu, am);

            // ---- numerator for this macro (chain-free) ----
            int L0A = lrA[0]; L0A = L0A < 0 ? 0 : L0A;
            int L0B = lrB[0]; L0B = L0B < 0 ? 0 : L0B;
            int PA = L0A, PB = L0B;
#pragma unroll
            for (int s = 1; s < 8; s++) {
                int LA = lrA[s]; LA = LA < 0 ? 0 : LA;
                int LB = lrB[s]; LB = LB < 0 ? 0 : LB;
                if (fast) {
                    numA += STRs[PA * 7 + LA] + rA[s * 7 + LA];  cntA++;
                    numB += STRs[PB * 7 + LB] + rB[s * 7 + LB];  cntB++;
                } else {
                    int MA = mrA[s], MB = mrB[s];
                    float vA = STRs[PA * 7 + LA] + rA[s * 7 + LA];
                    float vB = STRs[PB * 7 + LB] + rB[s * 7 + LB];
                    numA += MA ? vA : 0.f;  cntA += MA ? 1 : 0;
                    numB += MB ? vB : 0.f;  cntB += MB ? 1 : 0;
                }
                PA = LA; PB = LB;
            }
            // close pending cross-macro trans term with this macro's last label
            numA += pendMA ? STRs[PA * 7 + pendLA] : 0.f;
            numB += pendMB ? STRs[PB * 7 + pendLB] : 0.f;
            // s=0: emission now; trans term pends on the next (earlier) macro
            {
                int M0A = fast ? 1 : mrA[0];
                int M0B = fast ? 1 : mrB[0];
                numA += M0A ? rA[L0A] : 0.f;  cntA += M0A ? 1 : 0;
                numB += M0B ? rB[L0B] : 0.f;  cntB += M0B ? 1 : 0;
                pendLA = L0A; pendMA = M0A;
                pendLB = L0B; pendMB = M0B;
            }

            // ---- recursion (descending time) ----
            if (fast) {
#pragma unroll
                for (int s = 7; s >= 0; s--) BFSTEP(rA + s * 7, rB + s * 7);
            } else {
#pragma unroll
                for (int s = 7; s >= 0; s--) BSSTEP(rA + s * 7, rB + s * 7, mrA[s], mrB[s]);
            }
            RENORM();
            __syncwarp();
            if (k + 3 < 32) STAGE((k + 3) % 3, 63 - (k + 3)); else CP_COMMIT();
        }

        numA += pendMA ? STRs[L255A * 7 + pendLA] : 0.f;
        numB += pendMB ? STRs[L255B * 7 + pendLB] : 0.f;

        // ---- publish beta ----
        float aA[7], aB[7];
#pragma unroll
        for (int j = 0; j < 7; j++) UPK(p[j], aA[j], aB[j]);
#pragma unroll
        for (int j = 0; j < 7; j++) { gU[seqA * 8 + j] = aA[j]; gU[seqB * 8 + j] = aB[j]; }
        gXB[seqA] = xsA; gXB[seqB] = xsB;
        gNB[seqA] = numA; gNB[seqB] = numB;
        gCB[seqA] = cntA; gCB[seqB] = cntB;
    }

#undef STAGE
#undef RENORM
}

__global__ void __launch_bounds__(256)
combine_kernel(const int* __restrict__ labels,
               const float* __restrict__ endT,
               float* __restrict__ out)
{
    const int seq = blockIdx.x * 256 + threadIdx.x;
    float acc = 0.f;
#pragma unroll
    for (int j = 0; j < 7; j++) acc = fmaf(gA[seq * 8 + j], gU[seq * 8 + j], acc);
    float den = __logf(acc) + (float)(gXF[seq] + gXB[seq]) * 0.69314718055994531f;

    int c = gCF[seq] + gCB[seq];
    int li = c > 0 ? c - 1 : 0;
    int lt = __ldg(labels + (size_t)seq * Tv + li);
    lt = lt < 0 ? 0 : lt;
    float num = gNF[seq] + gNB[seq] + __ldg(endT + lt);

    float v = den - num;
#pragma unroll
    for (int off = 16; off > 0; off >>= 1)
        v += __shfl_xor_sync(0xFFFFFFFFu, v, off);
    if ((threadIdx.x & 31) == 0) atomicAdd(out, v);
}

extern "C" void kernel_launch(void* const* d_in, const int* in_sizes, int n_in,
                              void* d_out, int out_size)
{
    const float* em     = (const float*)d_in[0];
    const int*   labels = (const int*)  d_in[1];
    const int*   mask   = (const int*)  d_in[2];
    const float* startT = (const float*)d_in[3];
    const float* endT   = (const float*)d_in[4];
    const float* trans  = (const float*)d_in[5];

    cudaMemsetAsync(d_out, 0, sizeof(float));
    crf_half_kernel<<<256, 32>>>(em, labels, mask, startT, endT, trans);
    combine_kernel<<<32, 256>>>(labels, endT, (float*)d_out);
}